// round 16
// baseline (speedup 1.0000x reference)
#include <cuda_runtime.h>

// CosinLoss: loss = mean_i(1 - cos(pc_i, aug_i)). N=16384, D=1024 fp32 (128 MiB).
// K1: 4 rows per 256-thread CTA (64 thr/row, 4 float4/tensor/thread -> MLP_p1=8),
//     grid 4096, __ldcs streaming, launch_bounds(256,8) -> regs<=32, 8 CTAs/SM.
//     Epilogue: ONE fire-and-forget red.relaxed.gpu.add.u64 of the fixed-point CTA
//     partial into ONE OF 64 SHARDS (one 128B line each -> drain parallelizes over
//     64 L2 slices instead of serializing ~4096 ops on one atomic ALU, which R14/R15
//     showed costs ~4us at the kernel boundary).
// K2: 1 thread reads the 64 shard words (unrolled -> MLP 64, one L2 round trip),
//     integer-sums in fixed order (bit-deterministic), writes mean, re-zeros shards
//     for graph replay. Inter-kernel ordering makes all REDs visible; no fences.
// Quantization 2^-32 << 1e-3; shard sum < 64*8*2^32 = 2^41; total < 2^47.

#define CL_N   16384
#define CL_D   1024
#define CL_EPS 1e-12f
#define GRID1  4096
#define NSHARD 64
#define SHARD_STRIDE 16           // u64s; 128 B per shard line
#define FP_SCALE  4294967296.0    // 2^32

__device__ unsigned long long g_shard[NSHARD * SHARD_STRIDE];  // zero-init

__global__ __launch_bounds__(256, 8)
void cos_loss_main(const float* __restrict__ pc, const float* __restrict__ aug) {
    const int t    = threadIdx.x;
    const int wid  = t >> 5;        // 0..7; warps 2r,2r+1 own row r
    const int lane = t & 31;
    const int rsub = t >> 6;        // 0..3: row within CTA
    const int ct   = t & 63;        // thread index within row (64 thr/row)
    const size_t row = (size_t)blockIdx.x * 4 + rsub;

    const float4* __restrict__ p4 = reinterpret_cast<const float4*>(pc  + row * CL_D);
    const float4* __restrict__ a4 = reinterpret_cast<const float4*>(aug + row * CL_D);

    // 8 outstanding LDG.128 per thread, streaming hint.
    float4 p0 = __ldcs(&p4[ct      ]);
    float4 p1 = __ldcs(&p4[ct +  64]);
    float4 p2 = __ldcs(&p4[ct + 128]);
    float4 p3 = __ldcs(&p4[ct + 192]);
    float4 a0 = __ldcs(&a4[ct      ]);
    float4 a1 = __ldcs(&a4[ct +  64]);
    float4 a2 = __ldcs(&a4[ct + 128]);
    float4 a3 = __ldcs(&a4[ct + 192]);

    float dot = p0.x*a0.x + p0.y*a0.y + p0.z*a0.z + p0.w*a0.w
              + p1.x*a1.x + p1.y*a1.y + p1.z*a1.z + p1.w*a1.w
              + p2.x*a2.x + p2.y*a2.y + p2.z*a2.z + p2.w*a2.w
              + p3.x*a3.x + p3.y*a3.y + p3.z*a3.z + p3.w*a3.w;
    float npp = p0.x*p0.x + p0.y*p0.y + p0.z*p0.z + p0.w*p0.w
              + p1.x*p1.x + p1.y*p1.y + p1.z*p1.z + p1.w*p1.w
              + p2.x*p2.x + p2.y*p2.y + p2.z*p2.z + p2.w*p2.w
              + p3.x*p3.x + p3.y*p3.y + p3.z*p3.z + p3.w*p3.w;
    float naa = a0.x*a0.x + a0.y*a0.y + a0.z*a0.z + a0.w*a0.w
              + a1.x*a1.x + a1.y*a1.y + a1.z*a1.z + a1.w*a1.w
              + a2.x*a2.x + a2.y*a2.y + a2.z*a2.z + a2.w*a2.w
              + a3.x*a3.x + a3.y*a3.y + a3.z*a3.z + a3.w*a3.w;

    #pragma unroll
    for (int off = 16; off > 0; off >>= 1) {
        dot += __shfl_down_sync(0xFFFFFFFFu, dot, off);
        npp += __shfl_down_sync(0xFFFFFFFFu, npp, off);
        naa += __shfl_down_sync(0xFFFFFFFFu, naa, off);
    }

    __shared__ float s_dot[8], s_npp[8], s_naa[8];
    if (lane == 0) {
        s_dot[wid] = dot;
        s_npp[wid] = npp;
        s_naa[wid] = naa;
    }
    __syncthreads();

    // Warp 0, lanes 0..7: slot pairs (2r, 2r+1) belong to row r.
    if (wid == 0 && lane < 8) {
        dot = s_dot[lane];
        npp = s_npp[lane];
        naa = s_naa[lane];
        dot += __shfl_xor_sync(0x000000FFu, dot, 1);
        npp += __shfl_xor_sync(0x000000FFu, npp, 1);
        naa += __shfl_xor_sync(0x000000FFu, naa, 1);

        float loss = 0.0f;
        if ((lane & 1) == 0) {
            float np_ = fmaxf(sqrtf(npp), CL_EPS);
            float na_ = fmaxf(sqrtf(naa), CL_EPS);
            loss = 1.0f - dot / (np_ * na_);
        }
        loss += __shfl_down_sync(0x000000FFu, loss, 4);
        loss += __shfl_down_sync(0x000000FFu, loss, 2);

        if (lane == 0) {
            // Fixed-point encode; per-CTA partial in [0,8] -> fp < 2^35.
            unsigned long long fp =
                (unsigned long long)((double)loss * FP_SCALE + 0.5);
            // Fire-and-forget, sharded: 64-way parallel L2 drain.
            unsigned long long* dst =
                &g_shard[(blockIdx.x & (NSHARD - 1)) * SHARD_STRIDE];
            asm volatile("red.relaxed.gpu.global.add.u64 [%0], %1;"
                         :: "l"(dst), "l"(fp) : "memory");
        }
    }
}

// K2: read 64 shard words (unrolled -> deep MLP), finish, reset for replay.
__global__ __launch_bounds__(32)
void cos_loss_finish(float* __restrict__ out) {
    if (threadIdx.x == 0) {
        unsigned long long total = 0ULL;
        #pragma unroll
        for (int i = 0; i < NSHARD; i++)
            total += __ldcg(&g_shard[i * SHARD_STRIDE]);

        double sum = (double)total * (1.0 / FP_SCALE);
        out[0] = (float)(sum * (1.0 / (double)CL_N));

        #pragma unroll
        for (int i = 0; i < NSHARD; i++)
            asm volatile("st.global.cg.b64 [%0], %1;"
                         :: "l"(&g_shard[i * SHARD_STRIDE]), "l"(0ULL) : "memory");
    }
}

extern "C" void kernel_launch(void* const* d_in, const int* in_sizes, int n_in,
                              void* d_out, int out_size) {
    const float* pc  = (const float*)d_in[0];
    const float* aug = (const float*)d_in[1];
    float* out = (float*)d_out;

    cos_loss_main<<<GRID1, 256>>>(pc, aug);
    cos_loss_finish<<<1, 32>>>(out);
}

// round 17
// speedup vs baseline: 1.0694x; 1.0694x over previous
#include <cuda_runtime.h>

// CosinLoss: loss = mean_i(1 - cos(pc_i, aug_i)). N=16384, D=1024 fp32 (128 MiB).
// ZERO trailing kernels (R14-R16 proved any tiny trailing kernel costs ~4-5us fixed):
//   node 1: 4-byte D2D copy (allowed by harness rules) zeroes out[0] from a
//           __device__ float zero constant.
//   node 2: main kernel. 4 rows per 256-thread CTA (64 thr/row, 4 float4/tensor/
//           thread -> MLP_p1=8), grid 4096, __ldcs streaming, launch_bounds(256,8).
//           Epilogue: ONE fire-and-forget red.relaxed.gpu.add.f32 of loss/N into
//           out[0]. No return wait, no poller, no fences, no finish kernel.
// fp32 accumulation order varies ~1e-6 relative (vs 1e-3 tolerance); all work is
// identical every call. Kernel completion orders REDs before the next replay's copy.

#define CL_N   16384
#define CL_D   1024
#define CL_EPS 1e-12f
#define GRID1  4096

__device__ float g_zero = 0.0f;   // copy source for out[0] init

__global__ __launch_bounds__(256, 8)
void cos_loss_main(const float* __restrict__ pc, const float* __restrict__ aug,
                   float* __restrict__ out) {
    const int t    = threadIdx.x;
    const int wid  = t >> 5;        // 0..7; warps 2r,2r+1 own row r
    const int lane = t & 31;
    const int rsub = t >> 6;        // 0..3: row within CTA
    const int ct   = t & 63;        // thread index within row (64 thr/row)
    const size_t row = (size_t)blockIdx.x * 4 + rsub;

    const float4* __restrict__ p4 = reinterpret_cast<const float4*>(pc  + row * CL_D);
    const float4* __restrict__ a4 = reinterpret_cast<const float4*>(aug + row * CL_D);

    // 8 outstanding LDG.128 per thread, streaming hint.
    float4 p0 = __ldcs(&p4[ct      ]);
    float4 p1 = __ldcs(&p4[ct +  64]);
    float4 p2 = __ldcs(&p4[ct + 128]);
    float4 p3 = __ldcs(&p4[ct + 192]);
    float4 a0 = __ldcs(&a4[ct      ]);
    float4 a1 = __ldcs(&a4[ct +  64]);
    float4 a2 = __ldcs(&a4[ct + 128]);
    float4 a3 = __ldcs(&a4[ct + 192]);

    float dot = p0.x*a0.x + p0.y*a0.y + p0.z*a0.z + p0.w*a0.w
              + p1.x*a1.x + p1.y*a1.y + p1.z*a1.z + p1.w*a1.w
              + p2.x*a2.x + p2.y*a2.y + p2.z*a2.z + p2.w*a2.w
              + p3.x*a3.x + p3.y*a3.y + p3.z*a3.z + p3.w*a3.w;
    float npp = p0.x*p0.x + p0.y*p0.y + p0.z*p0.z + p0.w*p0.w
              + p1.x*p1.x + p1.y*p1.y + p1.z*p1.z + p1.w*p1.w
              + p2.x*p2.x + p2.y*p2.y + p2.z*p2.z + p2.w*p2.w
              + p3.x*p3.x + p3.y*p3.y + p3.z*p3.z + p3.w*p3.w;
    float naa = a0.x*a0.x + a0.y*a0.y + a0.z*a0.z + a0.w*a0.w
              + a1.x*a1.x + a1.y*a1.y + a1.z*a1.z + a1.w*a1.w
              + a2.x*a2.x + a2.y*a2.y + a2.z*a2.z + a2.w*a2.w
              + a3.x*a3.x + a3.y*a3.y + a3.z*a3.z + a3.w*a3.w;

    #pragma unroll
    for (int off = 16; off > 0; off >>= 1) {
        dot += __shfl_down_sync(0xFFFFFFFFu, dot, off);
        npp += __shfl_down_sync(0xFFFFFFFFu, npp, off);
        naa += __shfl_down_sync(0xFFFFFFFFu, naa, off);
    }

    __shared__ float s_dot[8], s_npp[8], s_naa[8];
    if (lane == 0) {
        s_dot[wid] = dot;
        s_npp[wid] = npp;
        s_naa[wid] = naa;
    }
    __syncthreads();

    // Warp 0, lanes 0..7: slot pairs (2r, 2r+1) belong to row r.
    if (wid == 0 && lane < 8) {
        dot = s_dot[lane];
        npp = s_npp[lane];
        naa = s_naa[lane];
        dot += __shfl_xor_sync(0x000000FFu, dot, 1);
        npp += __shfl_xor_sync(0x000000FFu, npp, 1);
        naa += __shfl_xor_sync(0x000000FFu, naa, 1);

        float loss = 0.0f;
        if ((lane & 1) == 0) {
            float np_ = fmaxf(sqrtf(npp), CL_EPS);
            float na_ = fmaxf(sqrtf(naa), CL_EPS);
            loss = 1.0f - dot / (np_ * na_);
        }
        loss += __shfl_down_sync(0x000000FFu, loss, 4);
        loss += __shfl_down_sync(0x000000FFu, loss, 2);

        if (lane == 0) {
            // Fire-and-forget: accumulate this CTA's contribution to the mean.
            float contrib = loss * (1.0f / (float)CL_N);
            asm volatile("red.relaxed.gpu.global.add.f32 [%0], %1;"
                         :: "l"(out), "f"(contrib) : "memory");
        }
    }
}

extern "C" void kernel_launch(void* const* d_in, const int* in_sizes, int n_in,
                              void* d_out, int out_size) {
    const float* pc  = (const float*)d_in[0];
    const float* aug = (const float*)d_in[1];
    float* out = (float*)d_out;

    // Node 1: zero out[0] via 4-byte device-to-device copy (graph-capturable,
    // explicitly allowed by the harness rules).
    void* zero_ptr = nullptr;
    cudaGetSymbolAddress(&zero_ptr, g_zero);
    cudaMemcpyAsync(d_out, zero_ptr, sizeof(float), cudaMemcpyDeviceToDevice, 0);

    // Node 2: the entire computation.
    cos_loss_main<<<GRID1, 256>>>(pc, aug, out);
}